// round 2
// baseline (speedup 1.0000x reference)
#include <cuda_runtime.h>
#include <stdint.h>

// DataEmbedder: out[row, 0:32]=emb0[lut0[ds[row,0]]], [32:96]=emb1[lut1[ds[row,1]]],
// [96:112]=emb2[lut2[ds[row,2]]], [112:120]=emb3[lut3[ds[row,3]]], [120:128]=ds[row,4:12]
// rows = 64*4096 = 262144, out = rows * 128 fp32 (= rows * 32 float4).

#define ROWS (64 * 4096)
#define RPW  4                  // rows per warp (ILP factor)
#define WPB  8                  // warps per block (256 threads)

__global__ __launch_bounds__(256)
void data_embedder_kernel(const float* __restrict__ dataset,
                          const float4* __restrict__ emb0,  // [1000, 8]  float4
                          const float4* __restrict__ emb1,  // [5000, 16] float4
                          const float4* __restrict__ emb2,  // [200, 4]   float4
                          const float4* __restrict__ emb3,  // [50, 2]    float4
                          const int* __restrict__ lut0,
                          const int* __restrict__ lut1,
                          const int* __restrict__ lut2,
                          const int* __restrict__ lut3,
                          float4* __restrict__ out)         // [rows, 32] float4
{
    const int lane = threadIdx.x & 31;
    const long long warp = (long long)blockIdx.x * WPB + (threadIdx.x >> 5);
    const long long row0 = warp * RPW;

    float4 v[RPW];

    if (lane < 8) {
        // emb0: 32 ch -> lanes 0..7
        #pragma unroll
        for (int r = 0; r < RPW; r++) {
            float raw = __ldcs(&dataset[(row0 + r) * 12]);
            int id = __ldg(&lut0[(int)raw]);
            v[r] = __ldg(&emb0[(long long)id * 8 + lane]);
        }
    } else if (lane < 24) {
        // emb1: 64 ch -> lanes 8..23
        #pragma unroll
        for (int r = 0; r < RPW; r++) {
            float raw = __ldcs(&dataset[(row0 + r) * 12 + 1]);
            int id = __ldg(&lut1[(int)raw]);
            v[r] = __ldg(&emb1[(long long)id * 16 + (lane - 8)]);
        }
    } else if (lane < 28) {
        // emb2: 16 ch -> lanes 24..27
        #pragma unroll
        for (int r = 0; r < RPW; r++) {
            float raw = __ldcs(&dataset[(row0 + r) * 12 + 2]);
            int id = __ldg(&lut2[(int)raw]);
            v[r] = __ldg(&emb2[(long long)id * 4 + (lane - 24)]);
        }
    } else if (lane < 30) {
        // emb3: 8 ch -> lanes 28..29
        #pragma unroll
        for (int r = 0; r < RPW; r++) {
            float raw = __ldcs(&dataset[(row0 + r) * 12 + 3]);
            int id = __ldg(&lut3[(int)raw]);
            v[r] = __ldg(&emb3[(long long)id * 2 + (lane - 28)]);
        }
    } else {
        // numeric passthrough: lane 30 -> cols 4..7, lane 31 -> cols 8..11
        // dataset row is 12 floats (48B, 16B-aligned): float4 index 1 or 2.
        const float4* ds4 = (const float4*)dataset;
        #pragma unroll
        for (int r = 0; r < RPW; r++) {
            v[r] = __ldcs(&ds4[(row0 + r) * 3 + (lane - 29)]);
        }
    }

    #pragma unroll
    for (int r = 0; r < RPW; r++) {
        __stcs(&out[(row0 + r) * 32 + lane], v[r]);
    }
}

extern "C" void kernel_launch(void* const* d_in, const int* in_sizes, int n_in,
                              void* d_out, int out_size)
{
    // Identify inputs by unique element counts (robust to metadata ordering).
    const float* dataset = nullptr;
    const void *e0 = nullptr, *e1 = nullptr, *e2 = nullptr, *e3 = nullptr;
    const int *l0 = nullptr, *l1 = nullptr, *l2 = nullptr, *l3 = nullptr;
    for (int i = 0; i < n_in; i++) {
        switch (in_sizes[i]) {
            case 64 * 4096 * 12: dataset = (const float*)d_in[i]; break;
            case 1000 * 32:      e0 = d_in[i]; break;
            case 5000 * 64:      e1 = d_in[i]; break;
            case 200 * 16:       e2 = d_in[i]; break;
            case 50 * 8:         e3 = d_in[i]; break;
            case 1000:           l0 = (const int*)d_in[i]; break;
            case 5000:           l1 = (const int*)d_in[i]; break;
            case 200:            l2 = (const int*)d_in[i]; break;
            case 50:             l3 = (const int*)d_in[i]; break;
            default: break;
        }
    }

    const int blocks = ROWS / (WPB * RPW);   // 8192
    data_embedder_kernel<<<blocks, 256>>>(
        dataset,
        (const float4*)e0, (const float4*)e1, (const float4*)e2, (const float4*)e3,
        l0, l1, l2, l3,
        (float4*)d_out);
}

// round 3
// speedup vs baseline: 1.9626x; 1.9626x over previous
#include <cuda_runtime.h>
#include <stdint.h>

// DataEmbedder: out[row, 0:32]=emb0[lut0[ds[row,0]]], [32:96]=emb1[lut1[ds[row,1]]],
// [96:112]=emb2[lut2[ds[row,2]]], [112:120]=emb3[lut3[ds[row,3]]], [120:128]=ds[row,4:12]
// rows = 64*4096 = 262144, out = rows * 128 fp32 (= rows * 32 float4).
//
// Branchless: per warp per row exactly 3 LDG + 1 STG.128:
//   LDG.128 #1: lanes 0-29 -> cats float4 (broadcast), lanes 30-31 -> numeric float4
//   LDG.32  #2: lut gather (per-lane lut pointer, broadcast within lane group)
//   LDG.128 #3: embedding gather (per-lane base+id*stride+sub*16); lanes 30-31 reload numeric
//   STG.128   : 512B contiguous output row

#define ROWS (64 * 4096)
#define RPW  4                  // rows per warp (ILP)
#define WPB  8                  // warps per block (256 threads)

__global__ __launch_bounds__(256)
void data_embedder_kernel(const float* __restrict__ dataset,
                          const char* __restrict__ emb0,   // [1000,32] f32 (128B/row)
                          const char* __restrict__ emb1,   // [5000,64] f32 (256B/row)
                          const char* __restrict__ emb2,   // [200,16]  f32 (64B/row)
                          const char* __restrict__ emb3,   // [50,8]    f32 (32B/row)
                          const int* __restrict__ lut0,
                          const int* __restrict__ lut1,
                          const int* __restrict__ lut2,
                          const int* __restrict__ lut3,
                          float4* __restrict__ out)        // [rows, 32] float4
{
    const int lane = threadIdx.x & 31;
    const long long warp = (long long)blockIdx.x * WPB + (threadIdx.x >> 5);
    const long long row0 = warp * RPW;

    // ---- per-lane constants (computed once; selects, no memory) ----
    // cls: 0:lanes0-7(emb0) 1:lanes8-23(emb1) 2:lanes24-27(emb2) 3:lanes28-29(emb3) 4:lanes30-31(numeric)
    const int cls = (lane < 8) ? 0 : (lane < 24) ? 1 : (lane < 28) ? 2 : (lane < 30) ? 3 : 4;
    const int sub = lane - ((cls == 0) ? 0 : (cls == 1) ? 8 : (cls == 2) ? 24 : (cls == 3) ? 28 : 29);
    const long long laneoff = (long long)sub * 16;   // byte offset of this lane's float4

    const int* lut = (cls == 0) ? lut0 : (cls == 1) ? lut1 : (cls == 2) ? lut2
                   : (cls == 3) ? lut3 : lut0;       // cls4: harmless (index clamped to 0)
    const char* base = (cls == 0) ? emb0 : (cls == 1) ? emb1 : (cls == 2) ? emb2 : emb3;
    const long long rowbytes = (cls == 0) ? 128 : (cls == 1) ? 256 : (cls == 2) ? 64 : 32;

    // first-load offset within the dataset row: cats (0) for lanes 0-29,
    // the lane's numeric float4 (16 or 32) for lanes 30-31.
    const long long off0 = (cls == 4) ? laneoff : 0;

    #pragma unroll
    for (int r = 0; r < RPW; r++) {
        const char* dsrow = (const char*)dataset + (row0 + r) * 48LL;

        // LDG #1: cats broadcast / numeric
        float4 first = __ldg((const float4*)(dsrow + off0));

        // component select (garbage for cls4, clamped below)
        float raw = (cls == 0) ? first.x : (cls == 1) ? first.y
                  : (cls == 2) ? first.z : first.w;
        int rawi = (cls == 4) ? 0 : (int)raw;

        // LDG #2: lut gather (broadcast within lane group)
        int id = __ldg(&lut[rawi]);

        // LDG #3: embedding gather / numeric reload (same addr as #1 for cls4 -> L1 hit)
        const char* p = (cls == 4) ? (dsrow + laneoff)
                                   : (base + (long long)id * rowbytes + laneoff);
        float4 v = __ldg((const float4*)p);

        // STG.128: contiguous 512B output row
        __stcs(&out[(row0 + r) * 32 + lane], v);
    }
}

extern "C" void kernel_launch(void* const* d_in, const int* in_sizes, int n_in,
                              void* d_out, int out_size)
{
    // Identify inputs by unique element counts (robust to metadata ordering).
    const float* dataset = nullptr;
    const void *e0 = nullptr, *e1 = nullptr, *e2 = nullptr, *e3 = nullptr;
    const int *l0 = nullptr, *l1 = nullptr, *l2 = nullptr, *l3 = nullptr;
    for (int i = 0; i < n_in; i++) {
        switch (in_sizes[i]) {
            case 64 * 4096 * 12: dataset = (const float*)d_in[i]; break;
            case 1000 * 32:      e0 = d_in[i]; break;
            case 5000 * 64:      e1 = d_in[i]; break;
            case 200 * 16:       e2 = d_in[i]; break;
            case 50 * 8:         e3 = d_in[i]; break;
            case 1000:           l0 = (const int*)d_in[i]; break;
            case 5000:           l1 = (const int*)d_in[i]; break;
            case 200:            l2 = (const int*)d_in[i]; break;
            case 50:             l3 = (const int*)d_in[i]; break;
            default: break;
        }
    }

    const int blocks = ROWS / (WPB * RPW);   // 8192
    data_embedder_kernel<<<blocks, 256>>>(
        dataset,
        (const char*)e0, (const char*)e1, (const char*)e2, (const char*)e3,
        l0, l1, l2, l3,
        (float4*)d_out);
}